// round 1
// baseline (speedup 1.0000x reference)
#include <cuda_runtime.h>
#include <cstdint>

// Problem constants
#define PC_B 512
#define PC_D 2048
#define PC_K 32

// Intermediate layer (F=64) scratch: [B][64][K] floats = 4 MB (static device mem, allowed)
__device__ float g_mid[(size_t)PC_B * 64 * PC_K];

__device__ __forceinline__ float warp_max(float v) {
#pragma unroll
    for (int o = 16; o > 0; o >>= 1)
        v = fmaxf(v, __shfl_xor_sync(0xffffffffu, v, o));
    return v;
}

__device__ __forceinline__ float warp_sum(float v) {
#pragma unroll
    for (int o = 16; o > 0; o >>= 1)
        v += __shfl_xor_sync(0xffffffffu, v, o);
    return v;
}

// One tree layer: for nodes j in [0,N), batches bl in [0,TB):
//   prod = vin[bl][2j][:] + vin[bl][2j+1][:]
//   out  = log( exp(prod - max) @ W[wbase + j] ) + max
// vin batch stride = in_bstride floats; vout layout [TB][N][32] compact.
// 16 warps per block. When N < 16, 16/N warps share a node and split batches.
// When N > 16, each warp loops over nodes j = w, w+16, ...
__device__ __forceinline__ void run_layer(
    const float* __restrict__ vin, size_t in_bstride,
    float* __restrict__ vout,
    const float* __restrict__ W, int wbase, int N, int TB,
    float* scr, int w, int lane)
{
    const int G = (N >= 16) ? 1 : (16 / N);
    const int g = (N >= 16) ? 0 : (w / N);
    for (int j = (N > 16 ? w : (w % N)); j < N; j += 16) {
        // Load this node's 32x32 weights into registers (column `lane`)
        const float* Wp = W + (size_t)(wbase + j) * (PC_K * PC_K) + lane;
        float wreg[32];
#pragma unroll
        for (int i = 0; i < 32; i++) wreg[i] = Wp[i * 32];

        for (int bl = g; bl < TB; bl += G) {
            const float* vp = vin + (size_t)bl * in_bstride + (size_t)(2 * j) * 32;
            float prod = vp[lane] + vp[32 + lane];
            float m = warp_max(prod);
            float e = __expf(prod - m);
            __syncwarp();
            scr[lane] = e;
            __syncwarp();
            float y0 = 0.f, y1 = 0.f;
            const float4* s4 = (const float4*)scr;
#pragma unroll
            for (int i = 0; i < 8; i++) {
                float4 v = s4[i];
                y0 = fmaf(v.x, wreg[4 * i + 0], y0);
                y1 = fmaf(v.y, wreg[4 * i + 1], y1);
                y0 = fmaf(v.z, wreg[4 * i + 2], y0);
                y1 = fmaf(v.w, wreg[4 * i + 3], y1);
            }
            vout[((size_t)bl * N + j) * 32 + lane] = __logf(y0 + y1) + m;
        }
    }
}

// ---------------------------------------------------------------------------
// Kernel A: layers F=1024 .. F=64.
// Grid: (64 subtrees of 32 leaves, 8 batch tiles of 64). 512 threads.
// Smem: valA [64][16][32], valB [64][8][32], scratch [16][32]  -> 198656 B
// ---------------------------------------------------------------------------
#define SMEM_A_FLOATS (64 * 16 * 32 + 64 * 8 * 32 + 16 * 32)

__global__ void __launch_bounds__(512, 1)
pc_kernel_A(const float* __restrict__ x, const float* __restrict__ W)
{
    extern __shared__ float sm[];
    float* valA = sm;                         // [64][16][32] max
    float* valB = sm + 64 * 16 * 32;          // [64][8][32] max
    float* scrb = valB + 64 * 8 * 32;         // [16][32]

    const int s   = blockIdx.x;   // subtree 0..63 (32 leaves each)
    const int bt  = blockIdx.y;   // batch tile 0..7
    const int tid = threadIdx.x;
    const int w = tid >> 5, lane = tid & 31;
    float* scr = scrb + w * 32;
    const int B0 = bt * 64;

    // Per-layer node counts (per subtree) and global weight-layer offsets
    const int Ns[5] = {16, 8, 4, 2, 1};
    const int Os[5] = {0, 1024, 1536, 1792, 1920};

    const float* vin = x + ((size_t)B0 * PC_D + (size_t)32 * s) * PC_K;
    size_t bstr = (size_t)PC_D * PC_K;
    float* bufs[2] = {valA, valB};

#pragma unroll
    for (int l = 0; l < 5; l++) {
        const int N = Ns[l];
        float* vout = bufs[l & 1];  // l even -> valA, odd -> valB
        run_layer(vin, bstr, vout, W, Os[l] + N * s, N, 64, scr, w, lane);
        __syncthreads();
        vin = vout;
        bstr = (size_t)N * 32;
    }

    // Final layer output (N=1) is in valA: [64][1][32] -> g_mid[b][s][k]
    for (int idx = tid; idx < 64 * 32; idx += 512) {
        const int bl = idx >> 5, k = idx & 31;
        g_mid[((size_t)(B0 + bl) * 64 + s) * 32 + k] = valA[bl * 32 + k];
    }
}

// ---------------------------------------------------------------------------
// Kernel B: layers F=32 .. F=1 + final mixture logsumexp.
// Grid: 64 blocks (TB=8 batches each), 512 threads.
// Smem: valA [8][32][32], valB [8][16][32], scratch [16][32] -> 51200 B
// ---------------------------------------------------------------------------
#define SMEM_B_FLOATS (8 * 32 * 32 + 8 * 16 * 32 + 16 * 32)

__global__ void __launch_bounds__(512, 1)
pc_kernel_B(const float* __restrict__ W, const float* __restrict__ mlw,
            float* __restrict__ out)
{
    extern __shared__ float sm[];
    float* valA = sm;                        // [8][32][32]
    float* valB = sm + 8 * 32 * 32;          // [8][16][32]
    float* scrb = valB + 8 * 16 * 32;        // [16][32]

    const int bt  = blockIdx.x;
    const int tid = threadIdx.x;
    const int w = tid >> 5, lane = tid & 31;
    float* scr = scrb + w * 32;
    const int B0 = bt * 8;

    const int Ns[6] = {32, 16, 8, 4, 2, 1};
    const int Os[6] = {1984, 2016, 2032, 2040, 2044, 2046};

    const float* vin = g_mid + (size_t)B0 * 64 * 32;
    size_t bstr = (size_t)64 * 32;
    float* bufs[2] = {valA, valB};

#pragma unroll
    for (int l = 0; l < 6; l++) {
        const int N = Ns[l];
        float* vout = bufs[l & 1];  // l0->valA ... l5->valB
        run_layer(vin, bstr, vout, W, Os[l], N, 8, scr, w, lane);
        __syncthreads();
        vin = vout;
        bstr = (size_t)N * 32;
    }

    // Root vectors in valB: [8][1][32]. Final: logsumexp(2*root + log_softmax(mlw))
    float lw = mlw[lane];
    float m2 = warp_max(lw);
    float ls = __logf(warp_sum(__expf(lw - m2))) + m2;
    float logw = lw - ls;

    if (w < 8) {
        const int bl = w;
        float t = 2.0f * valB[bl * 32 + lane] + logw;
        float mt = warp_max(t);
        float r = __logf(warp_sum(__expf(t - mt))) + mt;
        if (lane == 0) out[B0 + bl] = r;
    }
}

// ---------------------------------------------------------------------------
// Launch. Inputs (metadata order): x f32[512,2048,32], weights f32[2047,32,32],
// fold_idx i32[2047,2] (trivial (2f,2f+1) pairing -> computed directly),
// mix_logw f32[32]. Output: f32[512].
// ---------------------------------------------------------------------------
extern "C" void kernel_launch(void* const* d_in, const int* in_sizes, int n_in,
                              void* d_out, int out_size)
{
    const float* x   = (const float*)d_in[0];
    const float* W   = (const float*)d_in[1];
    const float* mlw = (const float*)d_in[3];
    float* out = (float*)d_out;

    cudaFuncSetAttribute(pc_kernel_A, cudaFuncAttributeMaxDynamicSharedMemorySize,
                         SMEM_A_FLOATS * sizeof(float));
    cudaFuncSetAttribute(pc_kernel_B, cudaFuncAttributeMaxDynamicSharedMemorySize,
                         SMEM_B_FLOATS * sizeof(float));

    pc_kernel_A<<<dim3(64, 8), 512, SMEM_A_FLOATS * sizeof(float)>>>(x, W);
    pc_kernel_B<<<64, 512, SMEM_B_FLOATS * sizeof(float)>>>(W, mlw, out);
}